// round 8
// baseline (speedup 1.0000x reference)
#include <cuda_runtime.h>
#include <cuda_bf16.h>

#define B 32
#define N 1024
#define EPSF 1.1920928955078125e-07f

// Scratch (device globals; no allocation allowed)
__device__ int g_rank[B * N];         // 0-based descending rank of a (true permutation)
__device__ float g_idcg_part[B * 4];  // per-(row,block) idcg partials
__device__ float g_loss_part[B * 4];  // per-(row,block) sum(a) partials

__device__ __forceinline__ float frcp(float x) {
    float r;
    asm("rcp.approx.f32 %0, %1;" : "=f"(r) : "f"(x));
    return r;
}

// ---------------------------------------------------------------------------
// prep: grid (4, B) x 256. Ranks via 64-bit composite keys
//   key = (monotone(a) << 10) | (1023 - idx)
// (distinct by construction; tie-break matches stable descending argsort).
// Also idcg + loss partials.
// ---------------------------------------------------------------------------
__global__ __launch_bounds__(256) void prep_kernel(const float* __restrict__ a,
                                                   const float* __restrict__ y) {
    const int row = blockIdx.y;
    const int bx = blockIdx.x;
    const int tid = threadIdx.x;
    const int base = row * N;

    __shared__ __align__(16) unsigned long long skey[N];  // 8KB
    __shared__ int cnt[5];
    __shared__ float red1[8];
    __shared__ float red2[8];

    if (tid < 5) cnt[tid] = 0;
    __syncthreads();

    // composite keys (descending a <=> descending key) + class histogram
    int lc[5] = {0, 0, 0, 0, 0};
#pragma unroll
    for (int s = 0; s < 4; s++) {
        const int idx = tid + s * 256;
        const unsigned int u = __float_as_uint(a[base + idx]);
        const unsigned int o = (u & 0x80000000u) ? ~u : (u | 0x80000000u);
        skey[idx] = ((unsigned long long)o << 10) | (unsigned int)(1023 - idx);
        const int yc = (int)y[base + idx];
#pragma unroll
        for (int v = 0; v < 5; v++) lc[v] += (yc == v);
    }
#pragma unroll
    for (int v = 0; v < 5; v++)
        if (lc[v]) atomicAdd(&cnt[v], lc[v]);
    __syncthreads();

    const int i = bx * 256 + tid;
    const unsigned long long mk = skey[i];

    // r0 = #{j : key_j > key_i}  (exact permutation, stable tie-break)
    int r0 = 0;
#pragma unroll 4
    for (int j = 0; j < N; j += 2) {
        const ulonglong2 k2 = *(const ulonglong2*)(skey + j);
        r0 += (k2.x > mk) + (k2.y > mk);
    }
    g_rank[base + i] = r0;

    // idcg contribution of ideal position i (descending-class boundaries),
    // full-precision discounts
    const int c4 = cnt[4];
    const int b3 = c4 + cnt[3];
    const int b2 = b3 + cnt[2];
    const int b1 = b2 + cnt[1];
    const int v = (i < c4) ? 4 : (i < b3) ? 3 : (i < b2) ? 2 : (i < b1) ? 1 : 0;
    float s1 = (float)((1 << v) - 1) / log2f((float)(i + 2));
    float s2 = a[base + i];

#pragma unroll
    for (int o = 16; o > 0; o >>= 1) {
        s1 += __shfl_down_sync(0xFFFFFFFFu, s1, o);
        s2 += __shfl_down_sync(0xFFFFFFFFu, s2, o);
    }
    const int wid = tid >> 5;
    const int lane = tid & 31;
    if (lane == 0) { red1[wid] = s1; red2[wid] = s2; }
    __syncthreads();
    if (tid == 0) {
        float t1 = 0.0f, t2 = 0.0f;
#pragma unroll
        for (int w = 0; w < 8; w++) { t1 += red1[w]; t2 += red2[w]; }
        g_idcg_part[row * 4 + bx] = t1;
        g_loss_part[row * 4 + bx] = t2;
    }
}

// ---------------------------------------------------------------------------
// grad inner sub-loop: fabs-free (sign known from L-crossing split), direct
// L subtraction, 2 pairs per rcp. Array element = {e, L}.
// MODE 0: n = (L_j - Li)*e_j   (dg>0, rank_j < rank_i)
// MODE 1: n = (Li - L_j)*e_j   (dg>0, rank_j > rank_i)
// MODE 2: n = L_j - Li         (dg<0, rank_j < rank_i)
// MODE 3: n = Li - L_j         (dg<0, rank_j > rank_i)
// ---------------------------------------------------------------------------
template <int MODE>
__device__ __forceinline__ float num_term(float e, float L, float Li) {
    if (MODE == 0) return (L - Li) * e;
    if (MODE == 1) return (Li - L) * e;
    if (MODE == 2) return L - Li;
    return Li - L;
}

template <int MODE>
__device__ __forceinline__ float seg_sum(const float2* __restrict__ s, int lo, int hi,
                                         float Li, float ei) {
    float sum = 0.0f;
    int j = lo;
    if (j < hi && (j & 1)) {
        const float2 v = s[j];
        sum = fmaf(num_term<MODE>(v.x, v.y, Li), frcp(ei + v.x), sum);
        j++;
    }
#pragma unroll 2
    for (; j + 1 < hi; j += 2) {
        const float4 v = *(const float4*)(s + j);
        const float n1 = num_term<MODE>(v.x, v.y, Li);
        const float n2 = num_term<MODE>(v.z, v.w, Li);
        const float d1 = ei + v.x;
        const float d2 = ei + v.z;
        sum = fmaf(fmaf(n1, d2, n2 * d1), frcp(d1 * d2), sum);
    }
    if (j < hi) {
        const float2 v = s[j];
        sum = fmaf(num_term<MODE>(v.x, v.y, Li), frcp(ei + v.x), sum);
    }
    return sum;
}

// ---------------------------------------------------------------------------
// grad: grid (4, B) x 512. Preamble builds the class-major/rank-ascending
// sorted row in shared (ballot counting sort over the exact rank
// permutation). Main loop: thread-half h covers half of each class segment;
// segments split at the L-crossing; dg constants hoisted; 2 pairs per rcp.
// ---------------------------------------------------------------------------
__global__ __launch_bounds__(512) void grad_kernel(const float* __restrict__ a,
                                                   const float* __restrict__ y,
                                                   float* __restrict__ out_grad,
                                                   float* loss_ptr) {
    const int row = blockIdx.y;
    const int tid = threadIdx.x;
    const int t = tid & 255;
    const int h = tid >> 8;
    const int base = row * N;
    const int wid = tid >> 5;
    const int lane = tid & 31;

    __shared__ float tmpE[N];                 // rank-indexed e
    __shared__ unsigned char scl[N];          // rank-indexed class
    __shared__ unsigned short toid[N];        // rank-indexed original idx
    __shared__ unsigned short soidx[N];       // sorted pos -> original idx
    __shared__ unsigned short srk[N];         // sorted pos -> r0 (0-based rank)
    __shared__ __align__(16) float2 sA[N];    // sorted {e, L}
    __shared__ unsigned int smask[32][5];     // per-chunk class ballot masks
    __shared__ unsigned short spref[33][5];   // exclusive chunk prefix counts
    __shared__ int soff[6];                   // class segment offsets
    __shared__ float comb[256];

    // Stage 1: scatter by rank (a-descending order); rank is a permutation
#pragma unroll
    for (int k = 0; k < 2; k++) {
        const int idx = tid + k * 512;
        const int r0 = g_rank[base + idx];
        tmpE[r0] = __expf(a[base + idx]);
        scl[r0] = (unsigned char)(int)y[base + idx];
        toid[r0] = (unsigned short)idx;
    }
    __syncthreads();

    // Stage 2: per-chunk class ballot masks (16 warps x 2 chunks)
#pragma unroll
    for (int c = 0; c < 2; c++) {
        const int ch = wid * 2 + c;
        const int v = (int)scl[ch * 32 + lane];
        const unsigned int b0 = __ballot_sync(0xFFFFFFFFu, v == 0);
        const unsigned int b1 = __ballot_sync(0xFFFFFFFFu, v == 1);
        const unsigned int b2 = __ballot_sync(0xFFFFFFFFu, v == 2);
        const unsigned int b3 = __ballot_sync(0xFFFFFFFFu, v == 3);
        const unsigned int b4 = __ballot_sync(0xFFFFFFFFu, v == 4);
        const unsigned int bb = (lane == 0) ? b0 : (lane == 1) ? b1 : (lane == 2) ? b2
                               : (lane == 3) ? b3 : b4;
        if (lane < 5) smask[ch][lane] = bb;
    }
    __syncthreads();

    // Stage 3: exclusive prefix over 32 chunks per class (warp 0)
    if (wid == 0) {
#pragma unroll
        for (int v = 0; v < 5; v++) {
            const int c = __popc(smask[lane][v]);
            int x = c;
#pragma unroll
            for (int o = 1; o < 32; o <<= 1) {
                const int tsh = __shfl_up_sync(0xFFFFFFFFu, x, o);
                if (lane >= o) x += tsh;
            }
            spref[lane][v] = (unsigned short)(x - c);
            if (lane == 31) spref[32][v] = (unsigned short)x;
        }
        __syncwarp();
        if (lane == 0) {
            int o = 0;
            soff[0] = 0;
#pragma unroll
            for (int c = 0; c < 5; c++) { o += (int)spref[32][c]; soff[c + 1] = o; }
        }
    }
    __syncthreads();

    // Stage 4: counting-sort scatter into class-major / rank-ascending order.
    // L computed at full precision (division + precise log2f).
#pragma unroll
    for (int k = 0; k < 2; k++) {
        const int q = tid + k * 512;  // q == r0 (a-sorted position)
        const int c = (int)scl[q];
        const int sp = (int)spref[q >> 5][c] +
                       __popc(smask[q >> 5][c] & ((1u << (q & 31)) - 1u));
        const int pos = soff[c] + sp;
        const float e = tmpE[q];
        const float L = 1.0f / log2f((float)(q + 2));
        sA[pos] = make_float2(e, L);
        soidx[pos] = toid[q];
        srk[pos] = (unsigned short)q;
    }

    // loss write (one block)
    if (loss_ptr && row == 0 && blockIdx.x == 0 && tid < 32) {
        float tl = 0.0f;
#pragma unroll
        for (int k = 0; k < 4; k++) tl += g_loss_part[tid + k * 32];
#pragma unroll
        for (int o = 16; o > 0; o >>= 1) tl += __shfl_down_sync(0xFFFFFFFFu, tl, o);
        if (tid == 0) *loss_ptr = tl;
    }
    __syncthreads();

    // Main loop
    const int p = blockIdx.x * 256 + t;
    const float2 mine = sA[p];
    const float ei = mine.x, Li = mine.y;
    const int ci = (p >= soff[1]) + (p >= soff[2]) + (p >= soff[3]) + (p >= soff[4]);
    const int r0 = (int)srk[p];
    const int chp = r0 >> 5;
    const unsigned int lmask = (1u << (r0 & 31)) - 1u;

    float acc = 0.0f;
#pragma unroll
    for (int sg = 0; sg < 5; sg++) {
        if (sg == ci) continue;
        const int beg = soff[sg];
        const int end = soff[sg + 1];
        // split: segment-sg elements with rank < rank_i (i.e. L_j > Li)
        const int m = beg + (int)spref[chp][sg] + __popc(smask[chp][sg] & lmask);
        const int half = (end - beg) >> 1;
        const int lo = beg + (h ? half : 0);
        const int hi = h ? end : beg + half;
        const int mc = (m < lo) ? lo : ((m > hi) ? hi : m);  // clamp to [lo,hi]

        if (sg < ci) {
            const float ss = seg_sum<0>(sA, lo, mc, Li, ei) +
                             seg_sum<1>(sA, mc, hi, Li, ei);
            acc = fmaf((float)((1 << ci) - (1 << sg)), ss, acc);
        } else {
            const float ss = seg_sum<2>(sA, lo, mc, Li, ei) +
                             seg_sum<3>(sA, mc, hi, Li, ei);
            acc = fmaf((float)((1 << ci) - (1 << sg)) * ei, ss, acc);
        }
    }

    if (h == 1) comb[t] = acc;
    __syncthreads();
    if (h == 0) {
        const float idcg = g_idcg_part[row * 4 + 0] + g_idcg_part[row * 4 + 1] +
                           g_idcg_part[row * 4 + 2] + g_idcg_part[row * 4 + 3];
        const float scale = -2.0f * frcp(idcg + EPSF);
        out_grad[base + (int)soidx[p]] = (acc + comb[t]) * scale;
    }
}

extern "C" void kernel_launch(void* const* d_in, const int* in_sizes, int n_in,
                              void* d_out, int out_size) {
    const float* a = (const float*)d_in[0];
    const float* y = (const float*)d_in[1];
    float* out = (float*)d_out;

    float* loss_ptr = nullptr;
    float* grad_ptr = out;
    if (out_size >= B * N + 1) {
        // flattened tuple: [loss, grad(32768)]
        loss_ptr = out;
        grad_ptr = out + 1;
    }

    prep_kernel<<<dim3(4, B), 256>>>(a, y);
    grad_kernel<<<dim3(4, B), 512>>>(a, y, grad_ptr, loss_ptr);
}

// round 9
// speedup vs baseline: 1.8657x; 1.8657x over previous
#include <cuda_runtime.h>
#include <cuda_bf16.h>

#define B 32
#define N 1024
#define EPSF 1.1920928955078125e-07f

// Scratch (device globals; no allocation allowed)
__device__ float2 g_eL[B * N];        // per original index {e=exp(a), L=1/log2(rank+1)}
__device__ float g_idcg_part[B * 4];  // per-(row,block) idcg partials
__device__ float g_loss_part[B * 4];  // per-(row,block) sum(a) partials

__device__ __forceinline__ float frcp(float x) {
    float r;
    asm("rcp.approx.f32 %0, %1;" : "=f"(r) : "f"(x));
    return r;
}

// ---------------------------------------------------------------------------
// prep: grid (4, B) x 256. Exact ranks via 64-bit composite keys
//   key = (monotone(a) << 10) | (1023 - idx)   (distinct; stable tie-break)
// Emits {e, L} per original index + idcg/loss partials.
// ---------------------------------------------------------------------------
__global__ __launch_bounds__(256) void prep_kernel(const float* __restrict__ a,
                                                   const float* __restrict__ y) {
    const int row = blockIdx.y;
    const int bx = blockIdx.x;
    const int tid = threadIdx.x;
    const int base = row * N;

    __shared__ __align__(16) unsigned long long skey[N];  // 8KB
    __shared__ int cnt[5];
    __shared__ float red1[8];
    __shared__ float red2[8];

    if (tid < 5) cnt[tid] = 0;
    __syncthreads();

    int lc[5] = {0, 0, 0, 0, 0};
#pragma unroll
    for (int s = 0; s < 4; s++) {
        const int idx = tid + s * 256;
        const unsigned int u = __float_as_uint(a[base + idx]);
        const unsigned int o = (u & 0x80000000u) ? ~u : (u | 0x80000000u);
        skey[idx] = ((unsigned long long)o << 10) | (unsigned int)(1023 - idx);
        const int yc = (int)y[base + idx];
#pragma unroll
        for (int v = 0; v < 5; v++) lc[v] += (yc == v);
    }
#pragma unroll
    for (int v = 0; v < 5; v++)
        if (lc[v]) atomicAdd(&cnt[v], lc[v]);
    __syncthreads();

    const int i = bx * 256 + tid;
    const unsigned long long mk = skey[i];

    // r0 = #{j : key_j > key_i}  (exact permutation)
    int r0 = 0;
#pragma unroll 4
    for (int j = 0; j < N; j += 2) {
        const ulonglong2 k2 = *(const ulonglong2*)(skey + j);
        r0 += (k2.x > mk) + (k2.y > mk);
    }

    const float ai = a[base + i];
    g_eL[base + i] = make_float2(__expf(ai), 1.0f / log2f((float)(r0 + 2)));

    // idcg contribution of ideal position i (descending-class boundaries)
    const int c4 = cnt[4];
    const int b3 = c4 + cnt[3];
    const int b2 = b3 + cnt[2];
    const int b1 = b2 + cnt[1];
    const int v = (i < c4) ? 4 : (i < b3) ? 3 : (i < b2) ? 2 : (i < b1) ? 1 : 0;
    float s1 = (float)((1 << v) - 1) / log2f((float)(i + 2));
    float s2 = ai;

#pragma unroll
    for (int o = 16; o > 0; o >>= 1) {
        s1 += __shfl_down_sync(0xFFFFFFFFu, s1, o);
        s2 += __shfl_down_sync(0xFFFFFFFFu, s2, o);
    }
    const int wid = tid >> 5;
    const int lane = tid & 31;
    if (lane == 0) { red1[wid] = s1; red2[wid] = s2; }
    __syncthreads();
    if (tid == 0) {
        float t1 = 0.0f, t2 = 0.0f;
#pragma unroll
        for (int w = 0; w < 8; w++) { t1 += red1[w]; t2 += red2[w]; }
        g_idcg_part[row * 4 + bx] = t1;
        g_loss_part[row * 4 + bx] = t2;
    }
}

// ---------------------------------------------------------------------------
// grad inner sub-loop: uniform bounds, fabs via free operand modifier,
// 2 pairs per rcp. MULE=true multiplies |dL| by e_j (dg>0 case).
// ---------------------------------------------------------------------------
template <bool MULE>
__device__ __forceinline__ float pair_term(float e, float L, float Li, float ei) {
    const float n = MULE ? (fabsf(Li - L) * e) : fabsf(Li - L);
    return n * frcp(ei + e);
}

template <bool MULE>
__device__ __forceinline__ float seg_sum(const float2* __restrict__ s, int lo, int hi,
                                         float Li, float ei) {
    float sum = 0.0f;
    int j = lo;
    if (j < hi && (j & 1)) { sum += pair_term<MULE>(s[j].x, s[j].y, Li, ei); j++; }
#pragma unroll 2
    for (; j + 1 < hi; j += 2) {
        const float4 v = *(const float4*)(s + j);
        float n1 = fabsf(Li - v.y);
        float n2 = fabsf(Li - v.w);
        if (MULE) { n1 *= v.x; n2 *= v.z; }
        const float d1 = ei + v.x;
        const float d2 = ei + v.z;
        sum = fmaf(fmaf(n1, d2, n2 * d1), frcp(d1 * d2), sum);
    }
    if (j < hi) sum += pair_term<MULE>(s[j].x, s[j].y, Li, ei);
    return sum;
}

// ---------------------------------------------------------------------------
// grad: grid (4, B) x 512. Preamble: ballot counting-sort by class (original-
// index order within class). Main loop: 5 class segments, uniform bounds,
// thread-half h covers half of each segment, dg constants hoisted.
// ---------------------------------------------------------------------------
__global__ __launch_bounds__(512) void grad_kernel(const float* __restrict__ y,
                                                   float* __restrict__ out_grad,
                                                   float* loss_ptr) {
    const int row = blockIdx.y;
    const int tid = threadIdx.x;
    const int t = tid & 255;
    const int h = tid >> 8;
    const int base = row * N;
    const int wid = tid >> 5;
    const int lane = tid & 31;

    __shared__ __align__(16) float2 sA[N];    // class-sorted {e, L}  (8KB)
    __shared__ unsigned short soidx[N];       // sorted pos -> original idx
    __shared__ unsigned int smask[32][5];     // per-chunk class ballot masks
    __shared__ unsigned short spref[33][5];   // exclusive chunk prefix counts
    __shared__ int soff[6];                   // class segment offsets
    __shared__ float comb[256];

    // Stage 1: per-chunk class ballots over original-index chunks.
    // Warp w handles chunks 2w, 2w+1 (indices 64w .. 64w+63).
    int mycls[2];
#pragma unroll
    for (int c = 0; c < 2; c++) {
        const int ch = wid * 2 + c;
        const int idx = ch * 32 + lane;
        const int v = (int)y[base + idx];
        mycls[c] = v;
        const unsigned int b0 = __ballot_sync(0xFFFFFFFFu, v == 0);
        const unsigned int b1 = __ballot_sync(0xFFFFFFFFu, v == 1);
        const unsigned int b2 = __ballot_sync(0xFFFFFFFFu, v == 2);
        const unsigned int b3 = __ballot_sync(0xFFFFFFFFu, v == 3);
        const unsigned int b4 = __ballot_sync(0xFFFFFFFFu, v == 4);
        const unsigned int bb = (lane == 0) ? b0 : (lane == 1) ? b1 : (lane == 2) ? b2
                               : (lane == 3) ? b3 : b4;
        if (lane < 5) smask[ch][lane] = bb;
    }
    __syncthreads();

    // Stage 2: exclusive prefix over 32 chunks per class (warp 0)
    if (wid == 0) {
#pragma unroll
        for (int v = 0; v < 5; v++) {
            const int c = __popc(smask[lane][v]);
            int x = c;
#pragma unroll
            for (int o = 1; o < 32; o <<= 1) {
                const int tsh = __shfl_up_sync(0xFFFFFFFFu, x, o);
                if (lane >= o) x += tsh;
            }
            spref[lane][v] = (unsigned short)(x - c);
            if (lane == 31) spref[32][v] = (unsigned short)x;
        }
        __syncwarp();
        if (lane == 0) {
            int o = 0;
            soff[0] = 0;
#pragma unroll
            for (int c = 0; c < 5; c++) { o += (int)spref[32][c]; soff[c + 1] = o; }
        }
    }
    __syncthreads();

    // Stage 3: counting-sort scatter into class-major order
#pragma unroll
    for (int c = 0; c < 2; c++) {
        const int ch = wid * 2 + c;
        const int idx = ch * 32 + lane;
        const int cl = mycls[c];
        const int sp = (int)spref[ch][cl] +
                       __popc(smask[ch][cl] & ((1u << lane) - 1u));
        const int pos = soff[cl] + sp;
        sA[pos] = g_eL[base + idx];
        soidx[pos] = (unsigned short)idx;
    }

    // loss write (one block)
    if (loss_ptr && row == 0 && blockIdx.x == 0 && tid < 32) {
        float tl = 0.0f;
#pragma unroll
        for (int k = 0; k < 4; k++) tl += g_loss_part[tid + k * 32];
#pragma unroll
        for (int o = 16; o > 0; o >>= 1) tl += __shfl_down_sync(0xFFFFFFFFu, tl, o);
        if (tid == 0) *loss_ptr = tl;
    }
    __syncthreads();

    // Main loop
    const int p = blockIdx.x * 256 + t;
    const float2 mine = sA[p];
    const float ei = mine.x, Li = mine.y;
    const int ci = (p >= soff[1]) + (p >= soff[2]) + (p >= soff[3]) + (p >= soff[4]);

    float acc = 0.0f;
#pragma unroll
    for (int sg = 0; sg < 5; sg++) {
        if (sg == ci) continue;
        const int beg = soff[sg];
        const int end = soff[sg + 1];
        const int mid = beg + ((end - beg) >> 1);
        const int lo = h ? mid : beg;
        const int hi = h ? end : mid;

        if (sg < ci) {
            // dg > 0: numerator |dL| * e_j
            acc = fmaf((float)((1 << ci) - (1 << sg)),
                       seg_sum<true>(sA, lo, hi, Li, ei), acc);
        } else {
            // dg < 0: numerator |dL| * e_i (e_i folded into segment constant)
            acc = fmaf((float)((1 << ci) - (1 << sg)) * ei,
                       seg_sum<false>(sA, lo, hi, Li, ei), acc);
        }
    }

    if (h == 1) comb[t] = acc;
    __syncthreads();
    if (h == 0) {
        const float idcg = g_idcg_part[row * 4 + 0] + g_idcg_part[row * 4 + 1] +
                           g_idcg_part[row * 4 + 2] + g_idcg_part[row * 4 + 3];
        const float scale = -2.0f * frcp(idcg + EPSF);
        out_grad[base + (int)soidx[p]] = (acc + comb[t]) * scale;
    }
}

extern "C" void kernel_launch(void* const* d_in, const int* in_sizes, int n_in,
                              void* d_out, int out_size) {
    const float* a = (const float*)d_in[0];
    const float* y = (const float*)d_in[1];
    float* out = (float*)d_out;

    float* loss_ptr = nullptr;
    float* grad_ptr = out;
    if (out_size >= B * N + 1) {
        // flattened tuple: [loss, grad(32768)]
        loss_ptr = out;
        grad_ptr = out + 1;
    }

    prep_kernel<<<dim3(4, B), 256>>>(a, y);
    grad_kernel<<<dim3(4, B), 512>>>(y, grad_ptr, loss_ptr);
}

// round 13
// speedup vs baseline: 2.1739x; 1.1652x over previous
#include <cuda_runtime.h>
#include <cuda_bf16.h>

#define B 32
#define N 1024
#define EPSF 1.1920928955078125e-07f

// Scratch (device globals; no allocation allowed)
__device__ float2 g_eL[B * N];        // per original index {e=exp(a), L=1/log2(rank+1)}
__device__ float g_idcg_part[B * 4];  // per-(row,block) idcg partials
__device__ float g_loss_part[B * 4];  // per-(row,block) sum(a) partials

__device__ __forceinline__ float frcp(float x) {
    float r;
    asm("rcp.approx.f32 %0, %1;" : "=f"(r) : "f"(x));
    return r;
}

// ---------------------------------------------------------------------------
// prep: grid (4, B) x 512. Exact ranks via 64-bit composite keys
//   key = (monotone(a) << 10) | (1023 - idx)   (distinct; stable tie-break)
// Each element's 1024-key scan is split across 2 threads (halves of the row).
// Emits {e, L} per original index + idcg/loss partials.
// ---------------------------------------------------------------------------
__global__ __launch_bounds__(512) void prep_kernel(const float* __restrict__ a,
                                                   const float* __restrict__ y) {
    const int row = blockIdx.y;
    const int bx = blockIdx.x;
    const int tid = threadIdx.x;
    const int t = tid & 255;
    const int half = tid >> 8;
    const int base = row * N;

    __shared__ __align__(16) unsigned long long skey[N];  // 8KB
    __shared__ int cnt[5];
    __shared__ int spart[256];
    __shared__ float red1[8];
    __shared__ float red2[8];

    if (tid < 5) cnt[tid] = 0;
    __syncthreads();

    // Build keys for the whole row (each thread: 2 elements) + class histogram
    int lc[5] = {0, 0, 0, 0, 0};
#pragma unroll
    for (int s = 0; s < 2; s++) {
        const int idx = tid + s * 512;
        const unsigned int u = __float_as_uint(a[base + idx]);
        const unsigned int o = (u & 0x80000000u) ? ~u : (u | 0x80000000u);
        skey[idx] = ((unsigned long long)o << 10) | (unsigned int)(1023 - idx);
        const int yc = (int)y[base + idx];
#pragma unroll
        for (int v = 0; v < 5; v++) lc[v] += (yc == v);
    }
#pragma unroll
    for (int v = 0; v < 5; v++)
        if (lc[v]) atomicAdd(&cnt[v], lc[v]);
    __syncthreads();

    // Partial rank of element i over key half [half*512, half*512+512)
    const int i = bx * 256 + t;
    const unsigned long long mk = skey[i];
    int r0p = 0;
    const int jbeg = half * 512;
#pragma unroll 4
    for (int j = jbeg; j < jbeg + 512; j += 2) {
        const ulonglong2 k2 = *(const ulonglong2*)(skey + j);
        r0p += (k2.x > mk) + (k2.y > mk);
    }
    if (half == 1) spart[t] = r0p;
    __syncthreads();

    if (half == 0) {
        const int r0 = r0p + spart[t];  // exact 0-based rank (permutation)
        const float ai = a[base + i];
        g_eL[base + i] = make_float2(__expf(ai), 1.0f / log2f((float)(r0 + 2)));

        // idcg contribution of ideal position i (descending-class boundaries)
        const int c4 = cnt[4];
        const int b3 = c4 + cnt[3];
        const int b2 = b3 + cnt[2];
        const int b1 = b2 + cnt[1];
        const int v = (i < c4) ? 4 : (i < b3) ? 3 : (i < b2) ? 2 : (i < b1) ? 1 : 0;
        float s1 = (float)((1 << v) - 1) / log2f((float)(i + 2));
        float s2 = ai;

#pragma unroll
        for (int o = 16; o > 0; o >>= 1) {
            s1 += __shfl_down_sync(0xFFFFFFFFu, s1, o);
            s2 += __shfl_down_sync(0xFFFFFFFFu, s2, o);
        }
        const int wid = tid >> 5;
        if ((tid & 31) == 0) { red1[wid] = s1; red2[wid] = s2; }
    }
    __syncthreads();
    if (tid == 0) {
        float t1 = 0.0f, t2 = 0.0f;
#pragma unroll
        for (int w = 0; w < 8; w++) { t1 += red1[w]; t2 += red2[w]; }
        g_idcg_part[row * 4 + bx] = t1;
        g_loss_part[row * 4 + bx] = t2;
    }
}

// ---------------------------------------------------------------------------
// Unified segment sum: S = sum |dL| / (ei+ej),  A = sum |dL|.
// Same body for every (thread, segment) — zero loop divergence.
// fabs is a free operand modifier; 2 pairs per rcp.
// ---------------------------------------------------------------------------
__device__ __forceinline__ float2 seg_sum(const float2* __restrict__ s, int lo, int hi,
                                          float Li, float ei) {
    float S = 0.0f, A = 0.0f;
    int j = lo;
    if (j < hi && (j & 1)) {
        const float2 v = s[j];
        const float n = fabsf(Li - v.y);
        A += n;
        S = fmaf(n, frcp(ei + v.x), S);
        j++;
    }
#pragma unroll 2
    for (; j + 1 < hi; j += 2) {
        const float4 v = *(const float4*)(s + j);
        const float n1 = fabsf(Li - v.y);
        const float n2 = fabsf(Li - v.w);
        const float d1 = ei + v.x;
        const float d2 = ei + v.z;
        A += n1 + n2;
        S = fmaf(fmaf(n1, d2, n2 * d1), frcp(d1 * d2), S);
    }
    if (j < hi) {
        const float2 v = s[j];
        const float n = fabsf(Li - v.y);
        A += n;
        S = fmaf(n, frcp(ei + v.x), S);
    }
    return make_float2(S, A);
}

// ---------------------------------------------------------------------------
// grad: grid (4, B) x 1024. Preamble: ballot counting-sort by class (one
// element per thread). Main loop: thread-quarter h covers a quarter of each
// class segment; unified body; per-segment O(1) predicated combine:
//   sg < ci (dg>0):  C * (A - ei*S)     [C = 2^ci - 2^sg > 0]
//   sg > ci (dg<0):  C * ei * S         [C < 0]
// ---------------------------------------------------------------------------
__global__ __launch_bounds__(1024) void grad_kernel(const float* __restrict__ y,
                                                    float* __restrict__ out_grad,
                                                    float* loss_ptr) {
    const int row = blockIdx.y;
    const int tid = threadIdx.x;
    const int t = tid & 255;
    const int h = tid >> 8;
    const int base = row * N;
    const int wid = tid >> 5;
    const int lane = tid & 31;

    __shared__ __align__(16) float2 sA[N];    // class-sorted {e, L}  (8KB)
    __shared__ unsigned short soidx[N];       // sorted pos -> original idx
    __shared__ unsigned int smask[32][5];     // per-chunk class ballot masks
    __shared__ unsigned short spref[33][5];   // exclusive chunk prefix counts
    __shared__ int soff[6];                   // class segment offsets
    __shared__ float comb[4][256];

    // Stage 1: per-chunk class ballots (warp w = chunk w, one element/thread)
    const int mycls = (int)y[base + tid];
    {
        const unsigned int b0 = __ballot_sync(0xFFFFFFFFu, mycls == 0);
        const unsigned int b1 = __ballot_sync(0xFFFFFFFFu, mycls == 1);
        const unsigned int b2 = __ballot_sync(0xFFFFFFFFu, mycls == 2);
        const unsigned int b3 = __ballot_sync(0xFFFFFFFFu, mycls == 3);
        const unsigned int b4 = __ballot_sync(0xFFFFFFFFu, mycls == 4);
        const unsigned int bb = (lane == 0) ? b0 : (lane == 1) ? b1 : (lane == 2) ? b2
                               : (lane == 3) ? b3 : b4;
        if (lane < 5) smask[wid][lane] = bb;
    }
    __syncthreads();

    // Stage 2: exclusive prefix over 32 chunks per class (warp 0)
    if (wid == 0) {
#pragma unroll
        for (int v = 0; v < 5; v++) {
            const int c = __popc(smask[lane][v]);
            int x = c;
#pragma unroll
            for (int o = 1; o < 32; o <<= 1) {
                const int tsh = __shfl_up_sync(0xFFFFFFFFu, x, o);
                if (lane >= o) x += tsh;
            }
            spref[lane][v] = (unsigned short)(x - c);
            if (lane == 31) spref[32][v] = (unsigned short)x;
        }
        __syncwarp();
        if (lane == 0) {
            int o = 0;
            soff[0] = 0;
#pragma unroll
            for (int c = 0; c < 5; c++) { o += (int)spref[32][c]; soff[c + 1] = o; }
        }
    }
    __syncthreads();

    // Stage 3: counting-sort scatter into class-major order
    {
        const int sp = (int)spref[wid][mycls] +
                       __popc(smask[wid][mycls] & ((1u << lane) - 1u));
        const int pos = soff[mycls] + sp;
        sA[pos] = g_eL[base + tid];
        soidx[pos] = (unsigned short)tid;
    }

    // loss write (one block)
    if (loss_ptr && row == 0 && blockIdx.x == 0 && tid < 32) {
        float tl = 0.0f;
#pragma unroll
        for (int k = 0; k < 4; k++) tl += g_loss_part[tid + k * 32];
#pragma unroll
        for (int o = 16; o > 0; o >>= 1) tl += __shfl_down_sync(0xFFFFFFFFu, tl, o);
        if (tid == 0) *loss_ptr = tl;
    }
    __syncthreads();

    // Main loop
    const int p = blockIdx.x * 256 + t;
    const float2 mine = sA[p];
    const float ei = mine.x, Li = mine.y;
    const int ci = (p >= soff[1]) + (p >= soff[2]) + (p >= soff[3]) + (p >= soff[4]);

    float acc = 0.0f;
#pragma unroll
    for (int sg = 0; sg < 5; sg++) {
        if (sg == ci) continue;
        const int beg = soff[sg];
        const int len = soff[sg + 1] - beg;
        const int lo = beg + ((len * h) >> 2);
        const int hi = beg + ((len * (h + 1)) >> 2);

        const float2 SA = seg_sum(sA, lo, hi, Li, ei);
        const float C = (float)((1 << ci) - (1 << sg));
        const float u = C * ei * SA.x;
        if (sg < ci) acc = fmaf(C, SA.y, acc) - u;   // C*(A - ei*S), C > 0
        else acc += u;                                // C*ei*S,      C < 0
    }

    comb[h][t] = acc;
    __syncthreads();
    if (h == 0) {
        const float idcg = g_idcg_part[row * 4 + 0] + g_idcg_part[row * 4 + 1] +
                           g_idcg_part[row * 4 + 2] + g_idcg_part[row * 4 + 3];
        const float scale = -2.0f * frcp(idcg + EPSF);
        const float total = acc + comb[1][t] + comb[2][t] + comb[3][t];
        out_grad[base + (int)soidx[p]] = total * scale;
    }
}

extern "C" void kernel_launch(void* const* d_in, const int* in_sizes, int n_in,
                              void* d_out, int out_size) {
    const float* a = (const float*)d_in[0];
    const float* y = (const float*)d_in[1];
    float* out = (float*)d_out;

    float* loss_ptr = nullptr;
    float* grad_ptr = out;
    if (out_size >= B * N + 1) {
        // flattened tuple: [loss, grad(32768)]
        loss_ptr = out;
        grad_ptr = out + 1;
    }

    prep_kernel<<<dim3(4, B), 512>>>(a, y);
    grad_kernel<<<dim3(4, B), 1024>>>(y, grad_ptr, loss_ptr);
}

// round 16
// speedup vs baseline: 2.3613x; 1.0862x over previous
#include <cuda_runtime.h>
#include <cuda_bf16.h>

#define B 32
#define N 1024
#define PADN (N + 80)
#define EPSF 1.1920928955078125e-07f
#define EPAD 1e18f

// Scratch (device globals; no allocation allowed)
__device__ float2 g_eL[B * N];        // per original index {e=exp(a), L=1/log2(rank+1)}
__device__ float g_idcg_part[B * 4];  // per-(row,block) idcg partials
__device__ float g_loss_part[B * 4];  // per-(row,block) sum(a) partials

__device__ __forceinline__ float frcp(float x) {
    float r;
    asm("rcp.approx.f32 %0, %1;" : "=f"(r) : "f"(x));
    return r;
}

// ---------------------------------------------------------------------------
// prep: grid (4, B) x 1024. Exact ranks via 64-bit composite keys
//   key = (monotone(a) << 10) | (1023 - idx)   (distinct; stable tie-break)
// Each element's 1024-key scan split across 4 threads (quarter scans).
// ---------------------------------------------------------------------------
__global__ __launch_bounds__(1024) void prep_kernel(const float* __restrict__ a,
                                                    const float* __restrict__ y) {
    const int row = blockIdx.y;
    const int bx = blockIdx.x;
    const int tid = threadIdx.x;
    const int t = tid & 255;
    const int q = tid >> 8;
    const int lane = tid & 31;
    const int base = row * N;

    __shared__ __align__(16) unsigned long long skey[N];  // 8KB
    __shared__ int cnt[5];
    __shared__ int spart[4][256];
    __shared__ float red1[8];
    __shared__ float red2[8];

    if (tid < 5) cnt[tid] = 0;
    __syncthreads();

    // one key per thread + warp-ballot histogram
    {
        const unsigned int u = __float_as_uint(a[base + tid]);
        const unsigned int o = (u & 0x80000000u) ? ~u : (u | 0x80000000u);
        skey[tid] = ((unsigned long long)o << 10) | (unsigned int)(1023 - tid);
        const int cls = (int)y[base + tid];
        const unsigned int b0 = __ballot_sync(0xFFFFFFFFu, cls == 0);
        const unsigned int b1 = __ballot_sync(0xFFFFFFFFu, cls == 1);
        const unsigned int b2 = __ballot_sync(0xFFFFFFFFu, cls == 2);
        const unsigned int b3 = __ballot_sync(0xFFFFFFFFu, cls == 3);
        const unsigned int b4 = __ballot_sync(0xFFFFFFFFu, cls == 4);
        const unsigned int bb = (lane == 0) ? b0 : (lane == 1) ? b1 : (lane == 2) ? b2
                               : (lane == 3) ? b3 : b4;
        if (lane < 5) atomicAdd(&cnt[lane], __popc(bb));
    }
    __syncthreads();

    // quarter scan: element i vs keys [256q, 256q+256)
    const int i = bx * 256 + t;
    const unsigned long long mk = skey[i];
    int r0p = 0;
    const int jbeg = q * 256;
#pragma unroll 4
    for (int j = jbeg; j < jbeg + 256; j += 2) {
        const ulonglong2 k2 = *(const ulonglong2*)(skey + j);
        r0p += (k2.x > mk) + (k2.y > mk);
    }
    spart[q][t] = r0p;
    __syncthreads();

    if (q == 0) {
        const int r0 = spart[0][t] + spart[1][t] + spart[2][t] + spart[3][t];
        const float ai = a[base + i];
        g_eL[base + i] = make_float2(__expf(ai), 1.0f / log2f((float)(r0 + 2)));

        // idcg contribution of ideal position i (descending-class boundaries)
        const int c4 = cnt[4];
        const int b3 = c4 + cnt[3];
        const int b2 = b3 + cnt[2];
        const int b1 = b2 + cnt[1];
        const int v = (i < c4) ? 4 : (i < b3) ? 3 : (i < b2) ? 2 : (i < b1) ? 1 : 0;
        float s1 = (float)((1 << v) - 1) / log2f((float)(i + 2));
        float s2 = ai;
#pragma unroll
        for (int o = 16; o > 0; o >>= 1) {
            s1 += __shfl_down_sync(0xFFFFFFFFu, s1, o);
            s2 += __shfl_down_sync(0xFFFFFFFFu, s2, o);
        }
        if (lane == 0) { red1[tid >> 5] = s1; red2[tid >> 5] = s2; }
    }
    __syncthreads();
    if (tid == 0) {
        float t1 = 0.0f, t2 = 0.0f;
#pragma unroll
        for (int w = 0; w < 8; w++) { t1 += red1[w]; t2 += red2[w]; }
        g_idcg_part[row * 4 + bx] = t1;
        g_loss_part[row * 4 + bx] = t2;
    }
}

// ---------------------------------------------------------------------------
// grad: grid (4, B) x 1024. Class-major counting sort with segments PADDED to
// multiples of 16 using sentinels {e=1e18, L=0}: every h-quarter is a
// branch-free, float4-aligned, stride-4 loop (no prologue/tail). Sentinel S
// contribution ~1e-18 (negligible); A contribution = Li per pad, removed by
// an exact O(1) correction. Per-segment combine:
//   sg < ci (dg>0):  C * (A - ei*S)     [C = 2^ci - 2^sg > 0]
//   sg > ci (dg<0):  C * ei * S         [C < 0]
// ---------------------------------------------------------------------------
__global__ __launch_bounds__(1024) void grad_kernel(const float* __restrict__ y,
                                                    float* __restrict__ out_grad,
                                                    float* loss_ptr) {
    const int row = blockIdx.y;
    const int tid = threadIdx.x;
    const int t = tid & 255;
    const int h = tid >> 8;
    const int base = row * N;
    const int wid = tid >> 5;
    const int lane = tid & 31;

    __shared__ __align__(16) float2 sA[PADN];  // padded class-sorted {e, L}
    __shared__ unsigned short soidx[PADN];     // sorted pos -> original idx
    __shared__ unsigned int smask[32][5];      // per-chunk class ballot masks
    __shared__ unsigned short spref[33][5];    // exclusive chunk prefix counts
    __shared__ int soff[6];                    // REAL class segment offsets
    __shared__ int poff[6];                    // PADDED segment offsets (mult of 16)
    __shared__ float comb[4][256];

    // Stage 1: per-chunk class ballots (warp w = chunk w)
    const int mycls = (int)y[base + tid];
    {
        const unsigned int b0 = __ballot_sync(0xFFFFFFFFu, mycls == 0);
        const unsigned int b1 = __ballot_sync(0xFFFFFFFFu, mycls == 1);
        const unsigned int b2 = __ballot_sync(0xFFFFFFFFu, mycls == 2);
        const unsigned int b3 = __ballot_sync(0xFFFFFFFFu, mycls == 3);
        const unsigned int b4 = __ballot_sync(0xFFFFFFFFu, mycls == 4);
        const unsigned int bb = (lane == 0) ? b0 : (lane == 1) ? b1 : (lane == 2) ? b2
                               : (lane == 3) ? b3 : b4;
        if (lane < 5) smask[wid][lane] = bb;
    }
    __syncthreads();

    // Stage 2: exclusive prefix over 32 chunks per class (warp 0) + offsets
    if (wid == 0) {
#pragma unroll
        for (int v = 0; v < 5; v++) {
            const int c = __popc(smask[lane][v]);
            int x = c;
#pragma unroll
            for (int o = 1; o < 32; o <<= 1) {
                const int tsh = __shfl_up_sync(0xFFFFFFFFu, x, o);
                if (lane >= o) x += tsh;
            }
            spref[lane][v] = (unsigned short)(x - c);
            if (lane == 31) spref[32][v] = (unsigned short)x;
        }
        __syncwarp();
        if (lane == 0) {
            int so = 0, po = 0;
            soff[0] = 0; poff[0] = 0;
#pragma unroll
            for (int c = 0; c < 5; c++) {
                const int n = (int)spref[32][c];
                so += n;
                po += (n + 15) & ~15;
                soff[c + 1] = so;
                poff[c + 1] = po;
            }
        }
    }
    __syncthreads();

    // Stage 3: counting-sort scatter into padded class-major slots + pad fill
    {
        const int sp = (int)spref[wid][mycls] +
                       __popc(smask[wid][mycls] & ((1u << lane) - 1u));
        const int pos = poff[mycls] + sp;
        sA[pos] = g_eL[base + tid];
        soidx[pos] = (unsigned short)tid;
    }
    if (tid < 80) {
        const int c = tid >> 4;
        const int k = tid & 15;
        const int realc = soff[c + 1] - soff[c];
        const int slot = poff[c] + realc + k;
        if (slot < poff[c + 1]) sA[slot] = make_float2(EPAD, 0.0f);
    }

    // loss write (one block)
    if (loss_ptr && row == 0 && blockIdx.x == 0 && tid < 32) {
        float tl = 0.0f;
#pragma unroll
        for (int k = 0; k < 4; k++) tl += g_loss_part[tid + k * 32];
#pragma unroll
        for (int o = 16; o > 0; o >>= 1) tl += __shfl_down_sync(0xFFFFFFFFu, tl, o);
        if (tid == 0) *loss_ptr = tl;
    }
    __syncthreads();

    // Main loop
    const int p = blockIdx.x * 256 + t;
    const int ci = (p >= soff[1]) + (p >= soff[2]) + (p >= soff[3]) + (p >= soff[4]);
    const int ppos = poff[ci] + (p - soff[ci]);
    const float2 mine = sA[ppos];
    const float ei = mine.x, Li = mine.y;

    float acc = 0.0f;
#pragma unroll
    for (int sg = 0; sg < 5; sg++) {
        if (sg == ci) continue;
        const int beg = poff[sg];
        const int qlen = (poff[sg + 1] - beg) >> 2;  // multiple of 4
        const int lo = beg + qlen * h;
        const int hi = lo + qlen;

        float S0 = 0.0f, S1 = 0.0f, A0 = 0.0f, A1 = 0.0f;
        for (int j = lo; j < hi; j += 4) {
            const float4 v0 = *(const float4*)(sA + j);
            const float4 v1 = *(const float4*)(sA + j + 2);
            const float n1 = fabsf(Li - v0.y);
            const float n2 = fabsf(Li - v0.w);
            const float d1 = ei + v0.x;
            const float d2 = ei + v0.z;
            A0 += n1 + n2;
            S0 = fmaf(fmaf(n1, d2, n2 * d1), frcp(d1 * d2), S0);
            const float n3 = fabsf(Li - v1.y);
            const float n4 = fabsf(Li - v1.w);
            const float d3 = ei + v1.x;
            const float d4 = ei + v1.z;
            A1 += n3 + n4;
            S1 = fmaf(fmaf(n3, d4, n4 * d3), frcp(d3 * d4), S1);
        }

        // exact pad correction: pads are the segment suffix, each adds Li to A
        const int ps = beg + (soff[sg + 1] - soff[sg]);
        const int pstart = (ps > lo) ? ps : lo;
        const int npad = (hi > pstart) ? (hi - pstart) : 0;
        const float A = A0 + A1 - (float)npad * Li;
        const float S = S0 + S1;

        const float C = (float)((1 << ci) - (1 << sg));
        const float u = C * ei * S;
        if (sg < ci) acc = fmaf(C, A, acc) - u;   // C*(A - ei*S), C > 0
        else acc += u;                             // C*ei*S,      C < 0
    }

    comb[h][t] = acc;
    __syncthreads();
    if (h == 0) {
        const float idcg = g_idcg_part[row * 4 + 0] + g_idcg_part[row * 4 + 1] +
                           g_idcg_part[row * 4 + 2] + g_idcg_part[row * 4 + 3];
        const float scale = -2.0f * frcp(idcg + EPSF);
        const float total = acc + comb[1][t] + comb[2][t] + comb[3][t];
        out_grad[base + (int)soidx[ppos]] = total * scale;
    }
}

extern "C" void kernel_launch(void* const* d_in, const int* in_sizes, int n_in,
                              void* d_out, int out_size) {
    const float* a = (const float*)d_in[0];
    const float* y = (const float*)d_in[1];
    float* out = (float*)d_out;

    float* loss_ptr = nullptr;
    float* grad_ptr = out;
    if (out_size >= B * N + 1) {
        // flattened tuple: [loss, grad(32768)]
        loss_ptr = out;
        grad_ptr = out + 1;
    }

    prep_kernel<<<dim3(4, B), 1024>>>(a, y);
    grad_kernel<<<dim3(4, B), 1024>>>(y, grad_ptr, loss_ptr);
}